// round 7
// baseline (speedup 1.0000x reference)
#include <cuda_runtime.h>
#include <math.h>

#define BB 128
#define QQ 500
#define NCLS 80
#define TT 64
#define FULL 0xffffffffu

__device__ __forceinline__ unsigned int f2ord(float f) {
    unsigned int u = __float_as_uint(f);
    return (u & 0x80000000u) ? ~u : (u | 0x80000000u);
}

// ================= Kernel A: cost matrix (bit-identical to best round) =================
#define KA_THREADS 256

__global__ __launch_bounds__(KA_THREADS)
void cost_kernel(const float* __restrict__ logits,   // [B,Q,C]
                 const float* __restrict__ pboxes,   // [B,Q,4]
                 const int*   __restrict__ tids,     // [B,T]
                 const float* __restrict__ tboxes,   // [B,T,4]
                 const float* __restrict__ imgsz,    // [B,4]
                 float*       __restrict__ out)      // [B,Q,T]
{
    __shared__ float4 s_tr[TT];
    __shared__ float4 s_tn[TT];
    __shared__ float  s_ta[TT];
    __shared__ int    s_cls[TT];

    const int b   = blockIdx.y;
    const int tid = threadIdx.x;

    const float inv0 = 1.0f / imgsz[b * 4 + 0];
    const float inv1 = 1.0f / imgsz[b * 4 + 1];
    const float inv2 = 1.0f / imgsz[b * 4 + 2];
    const float inv3 = 1.0f / imgsz[b * 4 + 3];

    if (tid < TT) {
        float4 tb = ((const float4*)tboxes)[b * TT + tid];
        s_tr[tid] = tb;
        s_tn[tid] = make_float4(tb.x * inv0, tb.y * inv1, tb.z * inv2, tb.w * inv3);
        s_ta[tid] = (tb.z - tb.x) * (tb.w - tb.y);
        s_cls[tid] = tids[b * TT + tid];
    }
    __syncthreads();

    const int t = tid & 63;
    const float4 tr = s_tr[t];
    const float4 tn = s_tn[t];
    const float  ta = s_ta[t];
    const int    cl = s_cls[t];

    const float* lg   = logits + (size_t)b * QQ * NCLS;
    float*       Cout = out    + (size_t)b * QQ * TT;

    #pragma unroll
    for (int rep = 0; rep < 8; rep++) {
        int q = blockIdx.x * 32 + rep * 4 + (tid >> 6);
        if (q >= QQ) break;

        float4 pb = ((const float4*)pboxes)[b * QQ + q];
        float bnx = pb.x * inv0, bny = pb.y * inv1;
        float bnz = pb.z * inv2, bnw = pb.w * inv3;
        float pa  = (pb.z - pb.x) * (pb.w - pb.y);

        float x = __ldg(lg + q * NCLS + cl);
        float p = 1.0f / (1.0f + expf(-x));
        float omp = 1.0f - p;
        float pos = 0.25f * omp * omp * (-logf(p + 1e-8f));
        float neg = 0.75f * p * p * (-log1pf(-p + 1e-8f));
        float ccost = pos - neg;

        float l1 = fabsf(bnx - tn.x) + fabsf(bny - tn.y)
                 + fabsf(bnz - tn.z) + fabsf(bnw - tn.w);

        float iwd = fmaxf(fminf(pb.z, tr.z) - fmaxf(pb.x, tr.x), 0.0f);
        float ihd = fmaxf(fminf(pb.w, tr.w) - fmaxf(pb.y, tr.y), 0.0f);
        float inter = iwd * ihd;
        float uni = pa + ta - inter;
        float iou = inter / uni;
        float ewd = fmaxf(fmaxf(pb.z, tr.z) - fminf(pb.x, tr.x), 0.0f);
        float ehd = fmaxf(fmaxf(pb.w, tr.w) - fminf(pb.y, tr.y), 0.0f);
        float enc = ewd * ehd;
        float giou = iou - (enc - uni) / enc;

        Cout[q * TT + t] = 5.0f * l1 + 2.0f * ccost - 2.0f * giou;
    }
}

// ================= Kernel B: greedy assignment with per-column top-8 caches =================
#define KB_THREADS 512

// dynamic smem layout (bytes)
#define OFF_PLIST 0                       // [16][64][8] u64 partial top-8 lists
#define OFF_TOPV  65536                   // [64][8] u32 values (f2ord)
#define OFF_TOPR  (OFF_TOPV + 2048)       // [64][8] u32 ravel
#define OFF_DEAD  (OFF_TOPR + 2048)       // [16] u32 dead-row bitmap
#define KB_SMEM   (OFF_DEAD + 64)

__device__ __forceinline__ void insert8(unsigned long long* l, unsigned long long k) {
    if (k < l[7]) {
        l[7] = k;
        #pragma unroll
        for (int i = 7; i > 0; i--) {
            if (l[i] < l[i - 1]) {
                unsigned long long tmp = l[i]; l[i] = l[i - 1]; l[i - 1] = tmp;
            }
        }
    }
}

__global__ __launch_bounds__(KB_THREADS, 1)
void assign_kernel(const float* __restrict__ C,    // [B,Q,T]
                   float*       __restrict__ out)
{
    extern __shared__ char smraw[];
    unsigned long long* s_plist = (unsigned long long*)(smraw + OFF_PLIST);
    unsigned* s_topv = (unsigned*)(smraw + OFF_TOPV);
    unsigned* s_topr = (unsigned*)(smraw + OFF_TOPR);
    unsigned* s_dead = (unsigned*)(smraw + OFF_DEAD);

    const int b = blockIdx.x, tid = threadIdx.x;
    const int lane = tid & 31, wrp = tid >> 5;
    const float* Cg = C + (size_t)b * QQ * TT;

    if (tid < 16) s_dead[tid] = 0u;

    // ---- Phase 1: streaming per-(warp,column) partial top-8 ----
    {
        unsigned long long l0[8], l1[8];
        #pragma unroll
        for (int k = 0; k < 8; k++) { l0[k] = ~0ull; l1[k] = ~0ull; }
        const int c0 = 2 * lane, c1 = 2 * lane + 1;

        #pragma unroll 4
        for (int k = 0; k < 32; k++) {
            int q = wrp + (k << 4);
            if (q >= QQ) break;
            float2 v = ((const float2*)(Cg + q * TT))[lane];   // coalesced
            unsigned long long k0 =
                ((unsigned long long)f2ord(v.x) << 15) | (unsigned)(q * TT + c0);
            unsigned long long k1 =
                ((unsigned long long)f2ord(v.y) << 15) | (unsigned)(q * TT + c1);
            insert8(l0, k0);
            insert8(l1, k1);
        }
        unsigned long long* pl = s_plist + ((wrp * TT + c0) << 3);
        #pragma unroll
        for (int k = 0; k < 8; k++) pl[k] = l0[k];
        pl = s_plist + ((wrp * TT + c1) << 3);
        #pragma unroll
        for (int k = 0; k < 8; k++) pl[k] = l1[k];
    }
    __syncthreads();

    // ---- Phase 2: merge 16 partials -> exact global top-8 per column ----
    // warp w merges columns 4w..4w+3; 128 candidates, 4 per lane.
    for (int cc = 0; cc < 4; cc++) {
        int col = (wrp << 2) + cc;
        unsigned long long k[4];
        #pragma unroll
        for (int m = 0; m < 4; m++) {
            int id = lane * 4 + m;            // 0..127
            k[m] = s_plist[(((id >> 3) * TT + col) << 3) + (id & 7)];
        }
        #pragma unroll
        for (int e = 0; e < 8; e++) {
            unsigned lv = 0xFFFFFFFFu;
            #pragma unroll
            for (int m = 0; m < 4; m++) {
                unsigned v = (unsigned)(k[m] >> 15);
                if (v < lv) lv = v;
            }
            unsigned mv = __reduce_min_sync(FULL, lv);
            unsigned lr = 0xFFFFFFFFu; int which = -1;
            #pragma unroll
            for (int m = 0; m < 4; m++) {
                if ((unsigned)(k[m] >> 15) == mv) {
                    unsigned r = (unsigned)(k[m] & 0x7FFFull);
                    if (r < lr) { lr = r; which = m; }
                }
            }
            unsigned mr = __reduce_min_sync(FULL, lr);
            if (which >= 0 && lr == mr) k[which] = ~0ull;   // (mv,mr) unique -> one lane
            if (lane == 0) { s_topv[col * 8 + e] = mv; s_topr[col * 8 + e] = mr; }
        }
    }
    __syncthreads();

    if (wrp != 0) return;   // greedy: warp 0 only (no __syncthreads beyond here)

    // ---- Phase 3: greedy, column cursors over top-8 lists ----
    unsigned v0 = s_topv[lane * 8],        r0 = s_topr[lane * 8];         // col = lane
    unsigned v1 = s_topv[(lane + 32) * 8], r1 = s_topr[(lane + 32) * 8];  // col = lane+32
    int p0 = 0, p1 = 0;
    const unsigned DEAD = 0xFFFFFFFFu;

    float* rows_out = out + (size_t)BB * QQ * TT + (size_t)b * TT;
    float* cols_out = rows_out + (size_t)BB * TT;

    #pragma unroll 1
    for (int s = 0; s < TT; s++) {
        unsigned m = __reduce_min_sync(FULL, v0 < v1 ? v0 : v1);
        unsigned cand = 0xFFFFFFFFu;
        if (v0 == m) cand = r0;
        if (v1 == m && r1 < cand) cand = r1;
        unsigned r = __reduce_min_sync(FULL, cand);   // exact (value, ravel) tie-break

        int i = (int)(r >> 6);
        int j = (int)(r & 63u);
        if (lane == 0) {
            rows_out[s] = (float)i;
            cols_out[s] = (float)j;
            s_dead[i >> 5] |= 1u << (i & 31);
        }
        if (s == TT - 1) break;

        // kill column j
        if (lane == (j & 31)) { if (j < 32) v0 = DEAD; else v1 = DEAD; }
        __syncwarp();

        // advance cursors of columns whose cached row was consumed
        bool x0 = false, x1 = false;
        if (v0 != DEAD && (r0 >> 6) == (unsigned)i) {
            int p = p0;
            while (++p < 8) {
                unsigned rr = s_topr[lane * 8 + p];
                unsigned q = rr >> 6;
                if (!((s_dead[q >> 5] >> (q & 31)) & 1u)) {
                    v0 = s_topv[lane * 8 + p]; r0 = rr; break;
                }
            }
            p0 = p;
            if (p >= 8) x0 = true;
        }
        if (v1 != DEAD && (r1 >> 6) == (unsigned)i) {
            int p = p1;
            while (++p < 8) {
                unsigned rr = s_topr[(lane + 32) * 8 + p];
                unsigned q = rr >> 6;
                if (!((s_dead[q >> 5] >> (q & 31)) & 1u)) {
                    v1 = s_topv[(lane + 32) * 8 + p]; r1 = rr; break;
                }
            }
            p1 = p;
            if (p >= 8) x1 = true;
        }

        // rare fallback: list exhausted -> full warp-cooperative gmem rescan
        unsigned bal0 = __ballot_sync(FULL, x0);
        unsigned bal1 = __ballot_sync(FULL, x1);
        while (bal0 | bal1) {
            int c;
            if (bal0) { c = __ffs(bal0) - 1; bal0 &= bal0 - 1; }
            else      { c = (__ffs(bal1) - 1) + 32; bal1 &= bal1 - 1; }

            unsigned best = 0xFFFFFFFFu, bq = 0;
            #pragma unroll
            for (int it = 0; it < 16; it++) {
                int q = lane + it * 32;
                if (q < QQ) {
                    unsigned dead = (s_dead[it] >> lane) & 1u;
                    float f = __ldg(Cg + q * TT + c);
                    unsigned u = dead ? 0xFFFFFFFFu : f2ord(f);
                    if (u < best) { best = u; bq = (unsigned)q; }
                }
            }
            unsigned mv = __reduce_min_sync(FULL, best);
            unsigned cr = (best == mv) ? ((bq << 6) | (unsigned)c) : 0xFFFFFFFFu;
            unsigned mr = __reduce_min_sync(FULL, cr);
            if (c < 32) { if (lane == c)      { v0 = mv; r0 = mr; } }
            else        { if (lane == c - 32) { v1 = mv; r1 = mr; } }
        }
    }
}

extern "C" void kernel_launch(void* const* d_in, const int* in_sizes, int n_in,
                              void* d_out, int out_size) {
    const float* logits = (const float*)d_in[0];   // [128,500,80]
    const float* pboxes = (const float*)d_in[1];   // [128,500,4]
    const int*   tids   = (const int*)  d_in[2];   // [128,64]
    const float* tboxes = (const float*)d_in[3];   // [128,64,4]
    const float* imgsz  = (const float*)d_in[4];   // [128,4]
    float* out = (float*)d_out;

    dim3 gA((QQ + 31) / 32, BB);
    cost_kernel<<<gA, KA_THREADS>>>(logits, pboxes, tids, tboxes, imgsz, out);

    cudaFuncSetAttribute(assign_kernel,
                         cudaFuncAttributeMaxDynamicSharedMemorySize, KB_SMEM);
    assign_kernel<<<BB, KB_THREADS, KB_SMEM>>>(out, out);
}

// round 8
// speedup vs baseline: 1.2607x; 1.2607x over previous
#include <cuda_runtime.h>
#include <math.h>

#define BB 128
#define QQ 500
#define NCLS 80
#define TT 64
#define FULL 0xffffffffu

__device__ __forceinline__ unsigned int f2ord(float f) {
    unsigned int u = __float_as_uint(f);
    return (u & 0x80000000u) ? ~u : (u | 0x80000000u);
}

// ================= Kernel A: cost matrix (bit-identical to best rounds) =================
#define KA_THREADS 256

__global__ __launch_bounds__(KA_THREADS)
void cost_kernel(const float* __restrict__ logits,   // [B,Q,C]
                 const float* __restrict__ pboxes,   // [B,Q,4]
                 const int*   __restrict__ tids,     // [B,T]
                 const float* __restrict__ tboxes,   // [B,T,4]
                 const float* __restrict__ imgsz,    // [B,4]
                 float*       __restrict__ out)      // [B,Q,T]
{
    __shared__ float4 s_tr[TT];
    __shared__ float4 s_tn[TT];
    __shared__ float  s_ta[TT];
    __shared__ int    s_cls[TT];

    const int b   = blockIdx.y;
    const int tid = threadIdx.x;

    const float inv0 = 1.0f / imgsz[b * 4 + 0];
    const float inv1 = 1.0f / imgsz[b * 4 + 1];
    const float inv2 = 1.0f / imgsz[b * 4 + 2];
    const float inv3 = 1.0f / imgsz[b * 4 + 3];

    if (tid < TT) {
        float4 tb = ((const float4*)tboxes)[b * TT + tid];
        s_tr[tid] = tb;
        s_tn[tid] = make_float4(tb.x * inv0, tb.y * inv1, tb.z * inv2, tb.w * inv3);
        s_ta[tid] = (tb.z - tb.x) * (tb.w - tb.y);
        s_cls[tid] = tids[b * TT + tid];
    }
    __syncthreads();

    const int t = tid & 63;
    const float4 tr = s_tr[t];
    const float4 tn = s_tn[t];
    const float  ta = s_ta[t];
    const int    cl = s_cls[t];

    const float* lg   = logits + (size_t)b * QQ * NCLS;
    float*       Cout = out    + (size_t)b * QQ * TT;

    #pragma unroll
    for (int rep = 0; rep < 8; rep++) {
        int q = blockIdx.x * 32 + rep * 4 + (tid >> 6);
        if (q >= QQ) break;

        float4 pb = ((const float4*)pboxes)[b * QQ + q];
        float bnx = pb.x * inv0, bny = pb.y * inv1;
        float bnz = pb.z * inv2, bnw = pb.w * inv3;
        float pa  = (pb.z - pb.x) * (pb.w - pb.y);

        float x = __ldg(lg + q * NCLS + cl);
        float p = 1.0f / (1.0f + expf(-x));
        float omp = 1.0f - p;
        float pos = 0.25f * omp * omp * (-logf(p + 1e-8f));
        float neg = 0.75f * p * p * (-log1pf(-p + 1e-8f));
        float ccost = pos - neg;

        float l1 = fabsf(bnx - tn.x) + fabsf(bny - tn.y)
                 + fabsf(bnz - tn.z) + fabsf(bnw - tn.w);

        float iwd = fmaxf(fminf(pb.z, tr.z) - fmaxf(pb.x, tr.x), 0.0f);
        float ihd = fmaxf(fminf(pb.w, tr.w) - fmaxf(pb.y, tr.y), 0.0f);
        float inter = iwd * ihd;
        float uni = pa + ta - inter;
        float iou = inter / uni;
        float ewd = fmaxf(fmaxf(pb.z, tr.z) - fminf(pb.x, tr.x), 0.0f);
        float ehd = fmaxf(fmaxf(pb.w, tr.w) - fminf(pb.y, tr.y), 0.0f);
        float enc = ewd * ehd;
        float giou = iou - (enc - uni) / enc;

        Cout[q * TT + t] = 5.0f * l1 + 2.0f * ccost - 2.0f * giou;
    }
}

// ================= Kernel B: assignment (smem mirror + cheap top-4 cursors) =================
#define KB_THREADS 1024
#define CSTR 513   // column-major stride: bank = (j+q)%32 -> conflict-free column scans

#define OFF_CM    0                          // [64][513] floats
#define OFF_TOPV  (TT * CSTR * 4)            // [64][4] u32 f2ord values
#define OFF_TOPR  (OFF_TOPV + TT * 4 * 4)    // [64][4] u32 ravel
#define OFF_DEAD  (OFF_TOPR + TT * 4 * 4)    // [16] u32 dead-row bitmap
#define KB_SMEM   (OFF_DEAD + 64)

__global__ __launch_bounds__(KB_THREADS, 1)
void assign_kernel(const float* __restrict__ C,    // [B,Q,T]
                   float*       __restrict__ out)
{
    extern __shared__ char smraw[];
    float*    Cm     = (float*)   (smraw + OFF_CM);
    unsigned* s_topv = (unsigned*)(smraw + OFF_TOPV);
    unsigned* s_topr = (unsigned*)(smraw + OFF_TOPR);
    unsigned* s_dead = (unsigned*)(smraw + OFF_DEAD);

    const int b = blockIdx.x, tid = threadIdx.x;
    const int lane = tid & 31, wrp = tid >> 5;
    const float* Cg = C + (size_t)b * QQ * TT;

    // ---- load + transpose: 8 independent float4 per thread (high MLP) ----
    #pragma unroll
    for (int k = 0; k < 8; k++) {
        int i = tid + k * KB_THREADS;        // < 8192
        float4 v = ((const float4*)Cg)[i];
        int q = i >> 4;
        int j = (i & 15) << 2;
        Cm[(j + 0) * CSTR + q] = v.x;
        Cm[(j + 1) * CSTR + q] = v.y;
        Cm[(j + 2) * CSTR + q] = v.z;
        Cm[(j + 3) * CSTR + q] = v.w;
    }
    if (tid < 16) s_dead[tid] = 0u;
    __syncthreads();

    // ---- init: exact top-4 per column; warp w owns columns 2w, 2w+1 ----
    #pragma unroll
    for (int cc = 0; cc < 2; cc++) {
        int col = wrp * 2 + cc;
        const float* p = Cm + col * CSTR;

        unsigned long long l0 = ~0ull, l1 = ~0ull, l2 = ~0ull, l3 = ~0ull;
        #pragma unroll
        for (int k = 0; k < 16; k++) {
            int q = lane + (k << 5);
            if (q < QQ) {
                unsigned long long key =
                    ((unsigned long long)f2ord(p[q]) << 15) | (unsigned)(q * TT + col);
                if (key < l3) {
                    l3 = key;
                    if (l3 < l2) { unsigned long long t_ = l3; l3 = l2; l2 = t_; }
                    if (l2 < l1) { unsigned long long t_ = l2; l2 = l1; l1 = t_; }
                    if (l1 < l0) { unsigned long long t_ = l1; l1 = l0; l0 = t_; }
                }
            }
        }
        #pragma unroll
        for (int e = 0; e < 4; e++) {
            unsigned lv = (unsigned)(l0 >> 15);
            unsigned mv = __reduce_min_sync(FULL, lv);
            unsigned lr = (lv == mv) ? (unsigned)(l0 & 0x7FFFull) : 0xFFFFFFFFu;
            unsigned mr = __reduce_min_sync(FULL, lr);
            if (lv == mv && (unsigned)(l0 & 0x7FFFull) == mr) {
                l0 = l1; l1 = l2; l2 = l3; l3 = ~0ull;   // pop head (unique lane)
            }
            if (lane == 0) { s_topv[col * 4 + e] = mv; s_topr[col * 4 + e] = mr; }
        }
    }
    __syncthreads();

    if (wrp != 0) return;   // greedy: warp 0 only (no __syncthreads beyond here)

    // ---- greedy: cursors over top-4 lists, smem colscan fallback ----
    unsigned v0 = s_topv[lane * 4],        r0 = s_topr[lane * 4];         // col = lane
    unsigned v1 = s_topv[(lane + 32) * 4], r1 = s_topr[(lane + 32) * 4];  // col = lane+32
    int p0 = 0, p1 = 0;
    const unsigned DEAD = 0xFFFFFFFFu;

    float* rows_out = out + (size_t)BB * QQ * TT + (size_t)b * TT;
    float* cols_out = rows_out + (size_t)BB * TT;

    #pragma unroll 1
    for (int s = 0; s < TT; s++) {
        unsigned m = __reduce_min_sync(FULL, v0 < v1 ? v0 : v1);
        unsigned cand = 0xFFFFFFFFu;
        if (v0 == m) cand = r0;
        if (v1 == m && r1 < cand) cand = r1;
        unsigned r = __reduce_min_sync(FULL, cand);   // exact (value, ravel) tie-break

        int i = (int)(r >> 6);
        int j = (int)(r & 63u);
        if (lane == 0) {
            rows_out[s] = (float)i;
            cols_out[s] = (float)j;
            s_dead[i >> 5] |= 1u << (i & 31);
        }
        if (s == TT - 1) break;

        // kill column j
        if (lane == (j & 31)) { if (j < 32) v0 = DEAD; else v1 = DEAD; }
        __syncwarp();   // s_dead update visible to all lanes

        // advance cursors of columns whose cached row was consumed
        bool x0 = false, x1 = false;
        if (v0 != DEAD && (r0 >> 6) == (unsigned)i) {
            int p = p0;
            while (++p < 4) {
                unsigned rr = s_topr[lane * 4 + p];
                unsigned q = rr >> 6;
                if (!((s_dead[q >> 5] >> (q & 31)) & 1u)) {
                    v0 = s_topv[lane * 4 + p]; r0 = rr; break;
                }
            }
            p0 = p;
            if (p >= 4) x0 = true;
        }
        if (v1 != DEAD && (r1 >> 6) == (unsigned)i) {
            int p = p1;
            while (++p < 4) {
                unsigned rr = s_topr[(lane + 32) * 4 + p];
                unsigned q = rr >> 6;
                if (!((s_dead[q >> 5] >> (q & 31)) & 1u)) {
                    v1 = s_topv[(lane + 32) * 4 + p]; r1 = rr; break;
                }
            }
            p1 = p;
            if (p >= 4) x1 = true;
        }

        // fallback (rare): exact masked colscan from smem
        unsigned bal0 = __ballot_sync(FULL, x0);
        unsigned bal1 = __ballot_sync(FULL, x1);
        while (bal0 | bal1) {
            int c;
            if (bal0) { c = __ffs(bal0) - 1; bal0 &= bal0 - 1; }
            else      { c = (__ffs(bal1) - 1) + 32; bal1 &= bal1 - 1; }

            const float* p = Cm + c * CSTR;
            unsigned best = 0xFFFFFFFFu, bq = 0;
            #pragma unroll
            for (int it = 0; it < 16; it++) {
                int q = lane + (it << 5);
                if (q < QQ) {
                    unsigned dead = (s_dead[it] >> lane) & 1u;
                    unsigned u = dead ? 0xFFFFFFFFu : f2ord(p[q]);
                    if (u < best) { best = u; bq = (unsigned)q; }
                }
            }
            unsigned mv = __reduce_min_sync(FULL, best);
            unsigned cr = (best == mv) ? ((bq << 6) | (unsigned)c) : 0xFFFFFFFFu;
            unsigned mr = __reduce_min_sync(FULL, cr);
            if (c < 32) { if (lane == c)      { v0 = mv; r0 = mr; } }
            else        { if (lane == c - 32) { v1 = mv; r1 = mr; } }
        }
    }
}

extern "C" void kernel_launch(void* const* d_in, const int* in_sizes, int n_in,
                              void* d_out, int out_size) {
    const float* logits = (const float*)d_in[0];   // [128,500,80]
    const float* pboxes = (const float*)d_in[1];   // [128,500,4]
    const int*   tids   = (const int*)  d_in[2];   // [128,64]
    const float* tboxes = (const float*)d_in[3];   // [128,64,4]
    const float* imgsz  = (const float*)d_in[4];   // [128,4]
    float* out = (float*)d_out;

    dim3 gA((QQ + 31) / 32, BB);
    cost_kernel<<<gA, KA_THREADS>>>(logits, pboxes, tids, tboxes, imgsz, out);

    cudaFuncSetAttribute(assign_kernel,
                         cudaFuncAttributeMaxDynamicSharedMemorySize, KB_SMEM);
    assign_kernel<<<BB, KB_THREADS, KB_SMEM>>>(out, out);
}

// round 9
// speedup vs baseline: 1.5219x; 1.2071x over previous
#include <cuda_runtime.h>
#include <math.h>

#define BB 128
#define QQ 500
#define NCLS 80
#define TT 64
#define NT 1024
#define CSTR 513   // column-major stride: bank = (col + q) % 32 -> conflict-free everywhere
#define FULL 0xffffffffu
#define SMEM_SZ (TT * CSTR * 4)   // 131,328 B dynamic (Cm only)

__device__ __forceinline__ unsigned f2ord(float f) {
    unsigned u = __float_as_uint(f);
    return (u & 0x80000000u) ? ~u : (u | 0x80000000u);
}

// warp-cooperative exact (value, ravel) min over one smem column
__device__ __forceinline__ void colscan(const float* __restrict__ Cm, int col,
                                        int lane, unsigned& mv, unsigned& mr) {
    const float* p = Cm + col * CSTR;
    unsigned best = 0xFFFFFFFFu, bq = 0;
    #pragma unroll
    for (int it = 0; it < 16; it++) {
        int q = lane + (it << 5);
        if (q < QQ) {
            unsigned u = f2ord(p[q]);
            if (u < best) { best = u; bq = (unsigned)q; }   // ascending q: min row on tie
        }
    }
    mv = __reduce_min_sync(FULL, best);
    unsigned cr = (best == mv) ? ((bq << 6) | (unsigned)col) : 0xFFFFFFFFu;
    mr = __reduce_min_sync(FULL, cr);
}

__global__ __launch_bounds__(NT, 1)
void hungarian_fused(const float* __restrict__ logits,   // [B,Q,C]
                     const float* __restrict__ pboxes,   // [B,Q,4]
                     const int*   __restrict__ tids,     // [B,T]
                     const float* __restrict__ tboxes,   // [B,T,4]
                     const float* __restrict__ imgsz,    // [B,4]
                     float*       __restrict__ out)
{
    extern __shared__ float Cm[];           // [64][513]
    __shared__ float4  s_tr[TT];
    __shared__ float4  s_tn[TT];
    __shared__ float   s_ta[TT];
    __shared__ int     s_cls[TT];
    __shared__ unsigned s_val[TT];
    __shared__ unsigned s_rav[TT];

    const int b = blockIdx.x, tid = threadIdx.x;
    const int lane = tid & 31, wrp = tid >> 5;

    const float inv0 = 1.0f / imgsz[b * 4 + 0];
    const float inv1 = 1.0f / imgsz[b * 4 + 1];
    const float inv2 = 1.0f / imgsz[b * 4 + 2];
    const float inv3 = 1.0f / imgsz[b * 4 + 3];

    if (tid < TT) {
        float4 tb = ((const float4*)tboxes)[b * TT + tid];
        s_tr[tid] = tb;
        s_tn[tid] = make_float4(tb.x * inv0, tb.y * inv1, tb.z * inv2, tb.w * inv3);
        s_ta[tid] = (tb.z - tb.x) * (tb.w - tb.y);
        s_cls[tid] = tids[b * TT + tid];
    }
    __syncthreads();

    // ---- Phase 1: cost matrix -> smem (col-major) + gmem, one pass ----
    const int t  = tid & 63;     // per-warp: q constant, t = lane + 32*(wrp&1)
    const int qg = tid >> 6;     // 16 q-groups
    const float4 tr = s_tr[t];
    const float4 tn = s_tn[t];
    const float  ta = s_ta[t];
    const int    cl = s_cls[t];

    const float* lg   = logits + (size_t)b * QQ * NCLS;
    float*       Cout = out    + (size_t)b * QQ * TT;

    #pragma unroll 4
    for (int k = 0; k < 32; k++) {
        int q = qg + (k << 4);
        if (q >= QQ) break;

        float4 pb = ((const float4*)pboxes)[b * QQ + q];   // uniform within warp
        float bnx = pb.x * inv0, bny = pb.y * inv1;
        float bnz = pb.z * inv2, bnw = pb.w * inv3;
        float pa  = (pb.z - pb.x) * (pb.w - pb.y);

        float x = __ldg(lg + q * NCLS + cl);
        float p = 1.0f / (1.0f + expf(-x));
        float omp = 1.0f - p;
        float pos = 0.25f * omp * omp * (-logf(p + 1e-8f));
        float neg = 0.75f * p * p * (-log1pf(-p + 1e-8f));
        float ccost = pos - neg;

        float l1 = fabsf(bnx - tn.x) + fabsf(bny - tn.y)
                 + fabsf(bnz - tn.z) + fabsf(bnw - tn.w);

        float iwd = fmaxf(fminf(pb.z, tr.z) - fmaxf(pb.x, tr.x), 0.0f);
        float ihd = fmaxf(fminf(pb.w, tr.w) - fmaxf(pb.y, tr.y), 0.0f);
        float inter = iwd * ihd;
        float uni = pa + ta - inter;
        float iou = inter / uni;
        float ewd = fmaxf(fmaxf(pb.z, tr.z) - fminf(pb.x, tr.x), 0.0f);
        float ehd = fmaxf(fmaxf(pb.w, tr.w) - fminf(pb.y, tr.y), 0.0f);
        float enc = ewd * ehd;
        float giou = iou - (enc - uni) / enc;

        float cost = 5.0f * l1 + 2.0f * ccost - 2.0f * giou;
        Cm[t * CSTR + q] = cost;     // conflict-free
        Cout[q * TT + t] = cost;     // coalesced (128B per warp)
    }
    __syncthreads();

    // ---- Phase 2: initial per-column (value, ravel) keys; warp w -> cols w, w+32 ----
    for (int c = wrp; c < TT; c += 32) {
        unsigned mv, mr;
        colscan(Cm, c, lane, mv, mr);
        if (lane == 0) { s_val[c] = mv; s_rav[c] = mr; }
    }
    __syncthreads();

    if (wrp != 0) return;   // greedy: warp 0 only

    // ---- Phase 3: greedy assignment (register keys, REDUX, poison-row) ----
    unsigned v0 = s_val[lane],      r0 = s_rav[lane];        // col = lane
    unsigned v1 = s_val[lane + 32], r1 = s_rav[lane + 32];   // col = lane+32
    const unsigned DEAD = 0xFFFFFFFFu;
    const float FINF = __int_as_float(0x7F800000);

    float* rows_out = out + (size_t)BB * QQ * TT + (size_t)b * TT;
    float* cols_out = rows_out + (size_t)BB * TT;

    #pragma unroll 1
    for (int s = 0; s < TT; s++) {
        unsigned m = __reduce_min_sync(FULL, v0 < v1 ? v0 : v1);
        unsigned cand = 0xFFFFFFFFu;
        if (v0 == m) cand = r0;
        if (v1 == m && r1 < cand) cand = r1;
        unsigned r = __reduce_min_sync(FULL, cand);   // exact (value, ravel) tie-break

        int i = (int)(r >> 6);
        int j = (int)(r & 63u);
        if (lane == 0) { rows_out[s] = (float)i; cols_out[s] = (float)j; }
        if (s == TT - 1) break;

        // kill column j
        if (lane == (j & 31)) { if (j < 32) v0 = DEAD; else v1 = DEAD; }

        // note rescan needs BEFORE poisoning reaches smem (register state only)
        bool n0 = (v0 != DEAD) && ((r0 >> 6) == (unsigned)i);
        bool n1 = (v1 != DEAD) && ((r1 >> 6) == (unsigned)i);

        // poison row i in every column -> future scans need no masking
        Cm[lane * CSTR + i] = FINF;
        Cm[(lane + 32) * CSTR + i] = FINF;

        unsigned bal0 = __ballot_sync(FULL, n0);
        unsigned bal1 = __ballot_sync(FULL, n1);
        if (bal0 | bal1) {
            __syncwarp();   // poisons visible before rescans
            while (bal0) {
                int c = __ffs(bal0) - 1; bal0 &= bal0 - 1;
                unsigned mv, mr;
                colscan(Cm, c, lane, mv, mr);
                if (lane == c) { v0 = mv; r0 = mr; }
            }
            while (bal1) {
                int c = __ffs(bal1) - 1; bal1 &= bal1 - 1;
                unsigned mv, mr;
                colscan(Cm, c + 32, lane, mv, mr);
                if (lane == c) { v1 = mv; r1 = mr; }
            }
        }
    }
}

extern "C" void kernel_launch(void* const* d_in, const int* in_sizes, int n_in,
                              void* d_out, int out_size) {
    const float* logits = (const float*)d_in[0];   // [128,500,80]
    const float* pboxes = (const float*)d_in[1];   // [128,500,4]
    const int*   tids   = (const int*)  d_in[2];   // [128,64]
    const float* tboxes = (const float*)d_in[3];   // [128,64,4]
    const float* imgsz  = (const float*)d_in[4];   // [128,4]
    float* out = (float*)d_out;

    cudaFuncSetAttribute(hungarian_fused,
                         cudaFuncAttributeMaxDynamicSharedMemorySize, SMEM_SZ);
    hungarian_fused<<<BB, NT, SMEM_SZ>>>(logits, pboxes, tids, tboxes, imgsz, out);
}